// round 1
// baseline (speedup 1.0000x reference)
#include <cuda_runtime.h>
#include <math.h>

#define N_NODES 50000
#define N_EDGES 600000
#define D 128
#define BN_EPS 1e-5f

// ---------------- scratch (static device globals; no allocation) ----------------
__device__ float  g_agg[(size_t)N_NODES * D];
__device__ float  g_h1 [(size_t)N_NODES * D];
__device__ float  g_h2 [(size_t)N_NODES * D];
__device__ double g_sum[D];
__device__ double g_sumsq[D];
__device__ float  g_scale[D];
__device__ float  g_shift[D];

// ---------------- K0: zero agg + BN accumulators ----------------
__global__ void zero_kernel() {
    size_t tid = (size_t)blockIdx.x * blockDim.x + threadIdx.x;
    size_t tot4 = (size_t)N_NODES * D / 4;
    size_t stride = (size_t)gridDim.x * blockDim.x;
    float4 z = make_float4(0.f, 0.f, 0.f, 0.f);
    for (size_t p = tid; p < tot4; p += stride) {
        reinterpret_cast<float4*>(g_agg)[p] = z;
    }
    if (tid < D) { g_sum[tid] = 0.0; g_sumsq[tid] = 0.0; }
}

// ---------------- K1: edge message + scatter-add ----------------
// One warp per edge; lane l handles float4 [4l, 4l+4).
__global__ void __launch_bounds__(256) edge_kernel(
    const float* __restrict__ x,
    const int*   __restrict__ edge_index,
    const float* __restrict__ edge_attr)
{
    int gw = (blockIdx.x * blockDim.x + threadIdx.x) >> 5;
    int lane = threadIdx.x & 31;
    if (gw >= N_EDGES) return;
    int src = edge_index[gw];
    int dst = edge_index[N_EDGES + gw];

    const float4 xv = *reinterpret_cast<const float4*>(&x[(size_t)src * D + lane * 4]);
    const float4 ev = *reinterpret_cast<const float4*>(&edge_attr[(size_t)gw * D + lane * 4]);
    float m0 = fmaxf(xv.x + ev.x, 0.f);
    float m1 = fmaxf(xv.y + ev.y, 0.f);
    float m2 = fmaxf(xv.z + ev.z, 0.f);
    float m3 = fmaxf(xv.w + ev.w, 0.f);

    float* dstp = &g_agg[(size_t)dst * D + lane * 4];
    asm volatile("red.global.add.v4.f32 [%0], {%1, %2, %3, %4};"
                 :: "l"(dstp), "f"(m0), "f"(m1), "f"(m2), "f"(m3) : "memory");
}

// ---------------- K2/K3: SGEMM  out[i][j] = sum_k in[i][k] * W[j][k] (+bias, epilogue)
// BM=64, BN=128, BK=16, 256 threads, micro-tile 8x4 per thread.
// LAYER 0: in = x + g_agg, out = relu(. + b1) -> g_h1
// LAYER 1: in = g_h1,      out = . + b2      -> g_h2, + BN column partial sums
template <int LAYER>
__global__ void __launch_bounds__(256) gemm_kernel(
    const float* __restrict__ X,      // x (layer0) / unused (layer1)
    const float* __restrict__ W,
    const float* __restrict__ bias)
{
    __shared__ float As[64 * 16];
    __shared__ float Bt[16 * 132];
    __shared__ float Rs[8 * 128];
    __shared__ float Rs2[8 * 128];

    const int t  = threadIdx.x;
    const int tx = t & 31;        // 32 col-groups of 4
    const int ty = t >> 5;        // 8 row-groups of 8
    const int rowBase = blockIdx.x * 64;

    float acc[8][4];
#pragma unroll
    for (int r = 0; r < 8; r++)
#pragma unroll
        for (int c = 0; c < 4; c++) acc[r][c] = 0.f;

    for (int k0 = 0; k0 < D; k0 += 16) {
        // --- load A tile (64x16), fused x+agg for layer 0 ---
        {
            int r  = t >> 2;
            int kg = t & 3;
            int gi = rowBase + r;
            float4 v = make_float4(0.f, 0.f, 0.f, 0.f);
            if (gi < N_NODES) {
                size_t off = (size_t)gi * D + k0 + kg * 4;
                if (LAYER == 0) {
                    float4 xv = *reinterpret_cast<const float4*>(&X[off]);
                    float4 av = *reinterpret_cast<const float4*>(&g_agg[off]);
                    v = make_float4(xv.x + av.x, xv.y + av.y, xv.z + av.z, xv.w + av.w);
                } else {
                    v = *reinterpret_cast<const float4*>(&g_h1[off]);
                }
            }
            *reinterpret_cast<float4*>(&As[r * 16 + kg * 4]) = v;
        }
        // --- load W tile transposed: Bt[kk][j] = W[j][k0+kk] ---
        for (int p = t; p < 512; p += 256) {
            int j  = p >> 2;
            int kg = p & 3;
            float4 w = *reinterpret_cast<const float4*>(&W[(size_t)j * D + k0 + kg * 4]);
            Bt[(kg * 4 + 0) * 132 + j] = w.x;
            Bt[(kg * 4 + 1) * 132 + j] = w.y;
            Bt[(kg * 4 + 2) * 132 + j] = w.z;
            Bt[(kg * 4 + 3) * 132 + j] = w.w;
        }
        __syncthreads();

#pragma unroll
        for (int kk = 0; kk < 16; kk++) {
            float4 b = *reinterpret_cast<const float4*>(&Bt[kk * 132 + tx * 4]);
            float br[4] = {b.x, b.y, b.z, b.w};
#pragma unroll
            for (int r = 0; r < 8; r++) {
                float a = As[(ty * 8 + r) * 16 + kk];
                acc[r][0] = fmaf(a, br[0], acc[r][0]);
                acc[r][1] = fmaf(a, br[1], acc[r][1]);
                acc[r][2] = fmaf(a, br[2], acc[r][2]);
                acc[r][3] = fmaf(a, br[3], acc[r][3]);
            }
        }
        __syncthreads();
    }

    // --- epilogue ---
    const int gj = tx * 4;
    float4 bv = *reinterpret_cast<const float4*>(&bias[gj]);
    float bb[4] = {bv.x, bv.y, bv.z, bv.w};

    if (LAYER == 0) {
#pragma unroll
        for (int r = 0; r < 8; r++) {
            int gi = rowBase + ty * 8 + r;
            if (gi < N_NODES) {
                float4 o;
                o.x = fmaxf(acc[r][0] + bb[0], 0.f);
                o.y = fmaxf(acc[r][1] + bb[1], 0.f);
                o.z = fmaxf(acc[r][2] + bb[2], 0.f);
                o.w = fmaxf(acc[r][3] + bb[3], 0.f);
                *reinterpret_cast<float4*>(&g_h1[(size_t)gi * D + gj]) = o;
            }
        }
    } else {
        float s[4]  = {0.f, 0.f, 0.f, 0.f};
        float s2[4] = {0.f, 0.f, 0.f, 0.f};
#pragma unroll
        for (int r = 0; r < 8; r++) {
            int gi = rowBase + ty * 8 + r;
            if (gi < N_NODES) {
                float v0 = acc[r][0] + bb[0];
                float v1 = acc[r][1] + bb[1];
                float v2 = acc[r][2] + bb[2];
                float v3 = acc[r][3] + bb[3];
                *reinterpret_cast<float4*>(&g_h2[(size_t)gi * D + gj]) =
                    make_float4(v0, v1, v2, v3);
                s[0] += v0; s[1] += v1; s[2] += v2; s[3] += v3;
                s2[0] += v0 * v0; s2[1] += v1 * v1; s2[2] += v2 * v2; s2[3] += v3 * v3;
            }
        }
#pragma unroll
        for (int c = 0; c < 4; c++) {
            Rs [ty * 128 + gj + c] = s[c];
            Rs2[ty * 128 + gj + c] = s2[c];
        }
        __syncthreads();
        if (t < 128) {
            float ssum = 0.f, ssq = 0.f;
#pragma unroll
            for (int r = 0; r < 8; r++) {
                ssum += Rs [r * 128 + t];
                ssq  += Rs2[r * 128 + t];
            }
            atomicAdd(&g_sum[t],   (double)ssum);
            atomicAdd(&g_sumsq[t], (double)ssq);
        }
    }
}

// ---------------- K4: BN finalize ----------------
__global__ void bn_finalize_kernel(const float* __restrict__ bn_w,
                                   const float* __restrict__ bn_b)
{
    int j = threadIdx.x;
    if (j >= D) return;
    double mean = g_sum[j] / (double)N_NODES;
    double var  = g_sumsq[j] / (double)N_NODES - mean * mean;
    if (var < 0.0) var = 0.0;
    float scale = bn_w[j] * rsqrtf((float)var + BN_EPS);
    g_scale[j] = scale;
    g_shift[j] = bn_b[j] - (float)mean * scale;
}

// ---------------- K5: BN apply + final ReLU -> d_out ----------------
__global__ void __launch_bounds__(256) apply_kernel(float* __restrict__ out)
{
    size_t p = (size_t)blockIdx.x * blockDim.x + threadIdx.x;
    size_t tot4 = (size_t)N_NODES * D / 4;
    if (p >= tot4) return;
    size_t e = p * 4;
    int col = (int)(e & (D - 1));
    float4 v = reinterpret_cast<const float4*>(g_h2)[p];
    float4 o;
    o.x = fmaxf(v.x * g_scale[col + 0] + g_shift[col + 0], 0.f);
    o.y = fmaxf(v.y * g_scale[col + 1] + g_shift[col + 1], 0.f);
    o.z = fmaxf(v.z * g_scale[col + 2] + g_shift[col + 2], 0.f);
    o.w = fmaxf(v.w * g_scale[col + 3] + g_shift[col + 3], 0.f);
    reinterpret_cast<float4*>(out)[p] = o;
}

// ---------------- launcher ----------------
extern "C" void kernel_launch(void* const* d_in, const int* in_sizes, int n_in,
                              void* d_out, int out_size)
{
    const float* x         = (const float*)d_in[0];
    const int*   edge_idx  = (const int*)  d_in[1];
    const float* edge_attr = (const float*)d_in[2];
    const float* w1        = (const float*)d_in[3];
    const float* b1        = (const float*)d_in[4];
    const float* w2        = (const float*)d_in[5];
    const float* b2        = (const float*)d_in[6];
    const float* bn_w      = (const float*)d_in[7];
    const float* bn_b      = (const float*)d_in[8];
    float* out = (float*)d_out;

    zero_kernel<<<1024, 256>>>();

    // one warp per edge
    int edge_blocks = (N_EDGES * 32 + 255) / 256;
    edge_kernel<<<edge_blocks, 256>>>(x, edge_idx, edge_attr);

    int gemm_blocks = (N_NODES + 63) / 64;
    gemm_kernel<0><<<gemm_blocks, 256>>>(x, w1, b1);
    gemm_kernel<1><<<gemm_blocks, 256>>>(nullptr, w2, b2);

    bn_finalize_kernel<<<1, 128>>>(bn_w, bn_b);

    size_t tot4 = (size_t)N_NODES * D / 4;
    int apply_blocks = (int)((tot4 + 255) / 256);
    apply_kernel<<<apply_blocks, 256>>>(out);
}

// round 3
// speedup vs baseline: 1.3243x; 1.3243x over previous
#include <cuda_runtime.h>
#include <cstdint>
#include <math.h>

#define N_NODES 50000
#define N_EDGES 600000
#define D 128
#define BN_EPS 1e-5f

#define BM 64
#define LDSS 132               // smem row stride (floats): 128 + 4 pad, 16B-aligned rows
#define GEMM_GRID 304
#define GEMM_SMEM ((D * LDSS + BM * LDSS + 2 * D) * 4)

// ---------------- scratch (static device globals; no allocation) ----------------
__device__ float  g_agg[(size_t)N_NODES * D];
__device__ float  g_h1 [(size_t)N_NODES * D];
__device__ float  g_h2 [(size_t)N_NODES * D];
__device__ double g_sum[D];
__device__ double g_sumsq[D];
__device__ float  g_scale[D];
__device__ float  g_shift[D];

// ---------------- K0: zero agg + BN accumulators ----------------
__global__ void zero_kernel() {
    size_t tid = (size_t)blockIdx.x * blockDim.x + threadIdx.x;
    size_t tot4 = (size_t)N_NODES * D / 4;
    size_t stride = (size_t)gridDim.x * blockDim.x;
    float4 z = make_float4(0.f, 0.f, 0.f, 0.f);
    for (size_t p = tid; p < tot4; p += stride) {
        reinterpret_cast<float4*>(g_agg)[p] = z;
    }
    if (tid < D) { g_sum[tid] = 0.0; g_sumsq[tid] = 0.0; }
}

// ---------------- K1: edge message + scatter-add ----------------
__global__ void __launch_bounds__(256) edge_kernel(
    const float* __restrict__ x,
    const int*   __restrict__ edge_index,
    const float* __restrict__ edge_attr)
{
    int gw = (blockIdx.x * blockDim.x + threadIdx.x) >> 5;
    int lane = threadIdx.x & 31;
    if (gw >= N_EDGES) return;
    int src = edge_index[gw];
    int dst = edge_index[N_EDGES + gw];

    const float4 xv = *reinterpret_cast<const float4*>(&x[(size_t)src * D + lane * 4]);
    const float4 ev = *reinterpret_cast<const float4*>(&edge_attr[(size_t)gw * D + lane * 4]);
    float m0 = fmaxf(xv.x + ev.x, 0.f);
    float m1 = fmaxf(xv.y + ev.y, 0.f);
    float m2 = fmaxf(xv.z + ev.z, 0.f);
    float m3 = fmaxf(xv.w + ev.w, 0.f);

    float* dstp = &g_agg[(size_t)dst * D + lane * 4];
    asm volatile("red.global.add.v4.f32 [%0], {%1, %2, %3, %4};"
                 :: "l"(dstp), "f"(m0), "f"(m1), "f"(m2), "f"(m3) : "memory");
}

// ---------------- tf32 helpers ----------------
__device__ __forceinline__ float to_tf32(float v) {
    uint32_t r;
    asm("cvt.rna.tf32.f32 %0, %1;" : "=r"(r) : "f"(v));
    return __uint_as_float(r);
}

__device__ __forceinline__ void mma_tf32(float& c0, float& c1, float& c2, float& c3,
                                         uint32_t a0, uint32_t a1, uint32_t a2, uint32_t a3,
                                         uint32_t b0, uint32_t b1)
{
    asm("mma.sync.aligned.m16n8k8.row.col.f32.tf32.tf32.f32 "
        "{%0,%1,%2,%3}, {%4,%5,%6,%7}, {%8,%9}, {%0,%1,%2,%3};"
        : "+f"(c0), "+f"(c1), "+f"(c2), "+f"(c3)
        : "r"(a0), "r"(a1), "r"(a2), "r"(a3), "r"(b0), "r"(b1));
}

// ---------------- K2/K3: tensor-core GEMM  out[i][j] = sum_k in[i][k] * W[j][k]
// Persistent CTAs. W staged in smem once per CTA (tf32). A tile 64x128 per iter.
// 8 warps as 2(M) x 4(N); warp tile 32x32 = 2 m-atoms x 4 n-atoms of m16n8k8.
// LAYER 0: in = x + g_agg, out = relu(. + b1) -> g_h1
// LAYER 1: in = g_h1,      out = . + b2      -> g_h2, + BN column sums
template <int LAYER>
__global__ void __launch_bounds__(256, 2) gemm_mma_kernel(
    const float* __restrict__ X,
    const float* __restrict__ W,
    const float* __restrict__ bias)
{
    extern __shared__ float smem[];
    float* Ws   = smem;                   // [D][LDSS]
    float* As   = smem + D * LDSS;        // [BM][LDSS]
    float* ColS = As + BM * LDSS;         // [D]
    float* ColS2= ColS + D;               // [D]

    const int t    = threadIdx.x;
    const int lane = t & 31;
    const int warp = t >> 5;
    const int g    = lane >> 2;   // group id 0..7
    const int c    = lane & 3;    // thread in group 0..3
    const int wm   = warp >> 2;   // 0..1  (M)
    const int wn   = warp & 3;    // 0..3  (N)

    // stage W (tf32) into smem
    for (int p = t; p < D * D / 4; p += 256) {
        int j = p >> 5;
        int k = (p & 31) << 2;
        float4 w = *reinterpret_cast<const float4*>(&W[(size_t)j * D + k]);
        float4 o = make_float4(to_tf32(w.x), to_tf32(w.y), to_tf32(w.z), to_tf32(w.w));
        *reinterpret_cast<float4*>(&Ws[j * LDSS + k]) = o;
    }
    if (LAYER == 1 && t < D) { ColS[t] = 0.f; ColS2[t] = 0.f; }

    // preload bias for this thread's 8 columns
    float bb0[4], bb1[4];
#pragma unroll
    for (int n = 0; n < 4; n++) {
        int col = wn * 32 + n * 8 + 2 * c;
        bb0[n] = bias[col];
        bb1[n] = bias[col + 1];
    }

    float bnS[8], bnS2[8];
    if (LAYER == 1) {
#pragma unroll
        for (int i = 0; i < 8; i++) { bnS[i] = 0.f; bnS2[i] = 0.f; }
    }
    __syncthreads();

    for (int tile = blockIdx.x; tile * BM < N_NODES; tile += gridDim.x) {
        const int rowBase = tile * BM;

        // ---- load A tile (64 x 128), tf32-converted ----
        for (int p = t; p < BM * D / 4; p += 256) {
            int r = p >> 5;
            int k = (p & 31) << 2;
            int gi = rowBase + r;
            float4 v = make_float4(0.f, 0.f, 0.f, 0.f);
            if (gi < N_NODES) {
                size_t off = (size_t)gi * D + k;
                if (LAYER == 0) {
                    float4 xv = *reinterpret_cast<const float4*>(&X[off]);
                    float4 av = *reinterpret_cast<const float4*>(&g_agg[off]);
                    v = make_float4(xv.x + av.x, xv.y + av.y, xv.z + av.z, xv.w + av.w);
                } else {
                    v = *reinterpret_cast<const float4*>(&g_h1[off]);
                }
            }
            float4 o = make_float4(to_tf32(v.x), to_tf32(v.y), to_tf32(v.z), to_tf32(v.w));
            *reinterpret_cast<float4*>(&As[r * LDSS + k]) = o;
        }
        __syncthreads();

        float acc[2][4][4];
#pragma unroll
        for (int m = 0; m < 2; m++)
#pragma unroll
            for (int n = 0; n < 4; n++)
#pragma unroll
                for (int i = 0; i < 4; i++) acc[m][n][i] = 0.f;

#pragma unroll
        for (int ks = 0; ks < 16; ks++) {
            const int k0 = ks * 8;
            uint32_t a[2][4];
#pragma unroll
            for (int m = 0; m < 2; m++) {
                const int rb = wm * 32 + m * 16;
                const float* base = &As[(rb + g) * LDSS + k0 + c];
                a[m][0] = __float_as_uint(base[0]);
                a[m][1] = __float_as_uint(base[8 * LDSS]);
                a[m][2] = __float_as_uint(base[4]);
                a[m][3] = __float_as_uint(base[8 * LDSS + 4]);
            }
#pragma unroll
            for (int n = 0; n < 4; n++) {
                const int jb = wn * 32 + n * 8 + g;
                uint32_t b0 = __float_as_uint(Ws[jb * LDSS + k0 + c]);
                uint32_t b1 = __float_as_uint(Ws[jb * LDSS + k0 + 4 + c]);
#pragma unroll
                for (int m = 0; m < 2; m++) {
                    mma_tf32(acc[m][n][0], acc[m][n][1], acc[m][n][2], acc[m][n][3],
                             a[m][0], a[m][1], a[m][2], a[m][3], b0, b1);
                }
            }
        }

        // ---- epilogue ----
#pragma unroll
        for (int m = 0; m < 2; m++) {
            const int r0 = rowBase + wm * 32 + m * 16 + g;
            const int r1 = r0 + 8;
#pragma unroll
            for (int n = 0; n < 4; n++) {
                const int col = wn * 32 + n * 8 + 2 * c;
                float v00 = acc[m][n][0] + bb0[n];
                float v01 = acc[m][n][1] + bb1[n];
                float v10 = acc[m][n][2] + bb0[n];
                float v11 = acc[m][n][3] + bb1[n];
                if (LAYER == 0) {
                    if (r0 < N_NODES) {
                        float2 o = make_float2(fmaxf(v00, 0.f), fmaxf(v01, 0.f));
                        *reinterpret_cast<float2*>(&g_h1[(size_t)r0 * D + col]) = o;
                    }
                    if (r1 < N_NODES) {
                        float2 o = make_float2(fmaxf(v10, 0.f), fmaxf(v11, 0.f));
                        *reinterpret_cast<float2*>(&g_h1[(size_t)r1 * D + col]) = o;
                    }
                } else {
                    if (r0 < N_NODES) {
                        *reinterpret_cast<float2*>(&g_h2[(size_t)r0 * D + col]) =
                            make_float2(v00, v01);
                        bnS [n * 2]     += v00;  bnS2[n * 2]     += v00 * v00;
                        bnS [n * 2 + 1] += v01;  bnS2[n * 2 + 1] += v01 * v01;
                    }
                    if (r1 < N_NODES) {
                        *reinterpret_cast<float2*>(&g_h2[(size_t)r1 * D + col]) =
                            make_float2(v10, v11);
                        bnS [n * 2]     += v10;  bnS2[n * 2]     += v10 * v10;
                        bnS [n * 2 + 1] += v11;  bnS2[n * 2 + 1] += v11 * v11;
                    }
                }
            }
        }
        __syncthreads();
    }

    if (LAYER == 1) {
#pragma unroll
        for (int n = 0; n < 4; n++) {
            const int col = wn * 32 + n * 8 + 2 * c;
            atomicAdd(&ColS [col],     bnS [n * 2]);
            atomicAdd(&ColS [col + 1], bnS [n * 2 + 1]);
            atomicAdd(&ColS2[col],     bnS2[n * 2]);
            atomicAdd(&ColS2[col + 1], bnS2[n * 2 + 1]);
        }
        __syncthreads();
        if (t < D) {
            atomicAdd(&g_sum[t],   (double)ColS[t]);
            atomicAdd(&g_sumsq[t], (double)ColS2[t]);
        }
    }
}

// ---------------- K4: BN finalize ----------------
__global__ void bn_finalize_kernel(const float* __restrict__ bn_w,
                                   const float* __restrict__ bn_b)
{
    int j = threadIdx.x;
    if (j >= D) return;
    double mean = g_sum[j] / (double)N_NODES;
    double var  = g_sumsq[j] / (double)N_NODES - mean * mean;
    if (var < 0.0) var = 0.0;
    float scale = bn_w[j] * rsqrtf((float)var + BN_EPS);
    g_scale[j] = scale;
    g_shift[j] = bn_b[j] - (float)mean * scale;
}

// ---------------- K5: BN apply + final ReLU -> d_out ----------------
__global__ void __launch_bounds__(256) apply_kernel(float* __restrict__ out)
{
    size_t p = (size_t)blockIdx.x * blockDim.x + threadIdx.x;
    size_t tot4 = (size_t)N_NODES * D / 4;
    if (p >= tot4) return;
    size_t e = p * 4;
    int col = (int)(e & (D - 1));
    float4 v = reinterpret_cast<const float4*>(g_h2)[p];
    float4 o;
    o.x = fmaxf(v.x * g_scale[col + 0] + g_shift[col + 0], 0.f);
    o.y = fmaxf(v.y * g_scale[col + 1] + g_shift[col + 1], 0.f);
    o.z = fmaxf(v.z * g_scale[col + 2] + g_shift[col + 2], 0.f);
    o.w = fmaxf(v.w * g_scale[col + 3] + g_shift[col + 3], 0.f);
    reinterpret_cast<float4*>(out)[p] = o;
}

// ---------------- launcher ----------------
extern "C" void kernel_launch(void* const* d_in, const int* in_sizes, int n_in,
                              void* d_out, int out_size)
{
    const float* x         = (const float*)d_in[0];
    const int*   edge_idx  = (const int*)  d_in[1];
    const float* edge_attr = (const float*)d_in[2];
    const float* w1        = (const float*)d_in[3];
    const float* b1        = (const float*)d_in[4];
    const float* w2        = (const float*)d_in[5];
    const float* b2        = (const float*)d_in[6];
    const float* bn_w      = (const float*)d_in[7];
    const float* bn_b      = (const float*)d_in[8];
    float* out = (float*)d_out;

    cudaFuncSetAttribute(gemm_mma_kernel<0>,
                         cudaFuncAttributeMaxDynamicSharedMemorySize, GEMM_SMEM);
    cudaFuncSetAttribute(gemm_mma_kernel<1>,
                         cudaFuncAttributeMaxDynamicSharedMemorySize, GEMM_SMEM);

    zero_kernel<<<1024, 256>>>();

    int edge_blocks = (N_EDGES * 32 + 255) / 256;
    edge_kernel<<<edge_blocks, 256>>>(x, edge_idx, edge_attr);

    gemm_mma_kernel<0><<<GEMM_GRID, 256, GEMM_SMEM>>>(x, w1, b1);
    gemm_mma_kernel<1><<<GEMM_GRID, 256, GEMM_SMEM>>>(nullptr, w2, b2);

    bn_finalize_kernel<<<1, 128>>>(bn_w, bn_b);

    size_t tot4 = (size_t)N_NODES * D / 4;
    int apply_blocks = (int)((tot4 + 255) / 256);
    apply_kernel<<<apply_blocks, 256>>>(out);
}